// round 4
// baseline (speedup 1.0000x reference)
#include <cuda_runtime.h>

// ---------------------------------------------------------------------------
// Fused, NON-persistent kernel (R2 grid geometry: 8192 blocks x 256 thr,
// one 2-row unit per block, no loop).
//
//   out[bt, n, d] = sum_m H[n,m] * x[bt, m, d]
//   x viewed as [BT=16384][M=4][DV=256 float4].
//
// Order inside a block:
//   1. all threads front-batch their 8 float4 stream loads (independent of H)
//   2. thread 0 computes the 4x4 Sinkhorn (scalar, row/col ILP, ~1200 cyc)
//      OVERLAPPED with the in-flight loads
//   3. __syncthreads, smem-broadcast H, FMA, streaming stores
// ---------------------------------------------------------------------------
__global__ __launch_bounds__(256) void fused_mix_kernel(
    const float* __restrict__ H_raw,
    const float4* __restrict__ x,
    float4* __restrict__ out)
{
    __shared__ float sh[16];

    const int unit = blockIdx.x;        // 2 bt rows per block
    const int q    = threadIdx.x;

    const float4* __restrict__ xa = x + (size_t)unit * 2048;   // bt = 2*unit
    const float4* __restrict__ xb = xa + 1024;                  // bt = 2*unit+1
    float4* __restrict__ oa       = out + (size_t)unit * 2048;
    float4* __restrict__ ob       = oa + 1024;

    // (1) Front-batch all 8 stream loads (MLP=8), evict-first.
    float4 a0 = __ldcs(xa + 0 * 256 + q);
    float4 a1 = __ldcs(xa + 1 * 256 + q);
    float4 a2 = __ldcs(xa + 2 * 256 + q);
    float4 a3 = __ldcs(xa + 3 * 256 + q);
    float4 b0 = __ldcs(xb + 0 * 256 + q);
    float4 b1 = __ldcs(xb + 1 * 256 + q);
    float4 b2 = __ldcs(xb + 2 * 256 + q);
    float4 b3 = __ldcs(xb + 3 * 256 + q);

    // (2) Thread 0: scalar Sinkhorn with 4-way row/col ILP, overlapped with
    //     the loads above (they are still in flight).
    if (q == 0) {
        float A[16];
        #pragma unroll
        for (int i = 0; i < 16; i++) A[i] = fabsf(__ldg(&H_raw[i])) + 1e-8f;

        #pragma unroll 1
        for (int it = 0; it < 20; it++) {
            #pragma unroll
            for (int i = 0; i < 4; i++) {
                float s = (A[4*i+0] + A[4*i+1]) + (A[4*i+2] + A[4*i+3]);
                float inv = __frcp_rn(s);
                #pragma unroll
                for (int j = 0; j < 4; j++) A[4*i+j] *= inv;
            }
            #pragma unroll
            for (int j = 0; j < 4; j++) {
                float s = (A[0+j] + A[4+j]) + (A[8+j] + A[12+j]);
                float inv = __frcp_rn(s);
                #pragma unroll
                for (int i = 0; i < 4; i++) A[4*i+j] *= inv;
            }
        }
        #pragma unroll
        for (int i = 0; i < 16; i++) sh[i] = A[i];
    }
    __syncthreads();

    // (3) Broadcast H (conflict-free smem broadcast) and mix.
    float h[16];
    #pragma unroll
    for (int i = 0; i < 16; i++) h[i] = sh[i];

    #pragma unroll
    for (int n = 0; n < 4; n++) {
        const float h0 = h[n * 4 + 0], h1 = h[n * 4 + 1];
        const float h2 = h[n * 4 + 2], h3 = h[n * 4 + 3];
        float4 o;
        o.x = h0 * a0.x + h1 * a1.x + h2 * a2.x + h3 * a3.x;
        o.y = h0 * a0.y + h1 * a1.y + h2 * a2.y + h3 * a3.y;
        o.z = h0 * a0.z + h1 * a1.z + h2 * a2.z + h3 * a3.z;
        o.w = h0 * a0.w + h1 * a1.w + h2 * a2.w + h3 * a3.w;
        __stcs(oa + n * 256 + q, o);
    }
    #pragma unroll
    for (int n = 0; n < 4; n++) {
        const float h0 = h[n * 4 + 0], h1 = h[n * 4 + 1];
        const float h2 = h[n * 4 + 2], h3 = h[n * 4 + 3];
        float4 o;
        o.x = h0 * b0.x + h1 * b1.x + h2 * b2.x + h3 * b3.x;
        o.y = h0 * b0.y + h1 * b1.y + h2 * b2.y + h3 * b3.y;
        o.z = h0 * b0.z + h1 * b1.z + h2 * b2.z + h3 * b3.z;
        o.w = h0 * b0.w + h1 * b1.w + h2 * b2.w + h3 * b3.w;
        __stcs(ob + n * 256 + q, o);
    }
}

extern "C" void kernel_launch(void* const* d_in, const int* in_sizes, int n_in,
                              void* d_out, int out_size) {
    const float* x     = (const float*)d_in[0];  // [4, 4096, 4, 1024] fp32
    const float* H_raw = (const float*)d_in[1];  // [4, 4]
    float* out         = (float*)d_out;          // [4, 4096, 4, 1024] fp32

    const int BT = 4 * 4096;  // 16384 (b,t) pairs, 2 per block
    fused_mix_kernel<<<BT / 2, 256>>>(H_raw, (const float4*)x, (float4*)out);
    (void)in_sizes; (void)n_in; (void)out_size;
}

// round 5
// speedup vs baseline: 1.5943x; 1.5943x over previous
#include <cuda_runtime.h>

// Device-global for the 4x4 doubly-stochastic matrix H.
__device__ float g_H[16];

// ---------------------------------------------------------------------------
// Kernel 1: warp-parallel Sinkhorn (proven ~2us in R2).
// Lane l<16 owns element (i=l/4, j=l%4). Row sums via shfl_xor width-4;
// col sums via shfl_xor {4,8} width-16. Fires the PDL trigger after the
// g_H writes are fenced, so the dependent mix kernel can pass its
// cudaGridDependencySynchronize().
// ---------------------------------------------------------------------------
__global__ void sinkhorn_kernel(const float* __restrict__ H_raw) {
    const int l = threadIdx.x;
    const int e = l & 15;
    float a = fabsf(H_raw[e]) + 1e-8f;

    #pragma unroll 1
    for (int it = 0; it < 20; it++) {
        float s = a;
        s += __shfl_xor_sync(0xFFFFFFFFu, s, 1, 4);
        s += __shfl_xor_sync(0xFFFFFFFFu, s, 2, 4);
        a *= __frcp_rn(s);
        float c = a;
        c += __shfl_xor_sync(0xFFFFFFFFu, c, 4, 16);
        c += __shfl_xor_sync(0xFFFFFFFFu, c, 8, 16);
        a *= __frcp_rn(c);
    }

    if (l < 16) g_H[l] = a;
    __threadfence();
    cudaTriggerProgrammaticLaunchCompletion();
}

// ---------------------------------------------------------------------------
// Kernel 2: R2's proven streaming mix (74us, 82% DRAM), with one change:
// the 8 front-batched loads are issued BEFORE cudaGridDependencySynchronize(),
// so the wait on the sinkhorn kernel overlaps with the loads in flight.
// No barrier, no per-block serial chain — block body is otherwise identical.
// ---------------------------------------------------------------------------
__global__ __launch_bounds__(256) void mix_kernel(const float4* __restrict__ x,
                                                  float4* __restrict__ out) {
    const int bt0 = blockIdx.x * 2;
    const int q   = threadIdx.x;

    const float4* __restrict__ xa = x + (size_t)bt0 * 1024;
    const float4* __restrict__ xb = xa + 1024;
    float4* __restrict__ oa       = out + (size_t)bt0 * 1024;
    float4* __restrict__ ob       = oa + 1024;

    // Front-batch all 8 stream loads (MLP=8), evict-first. Independent of H.
    float4 a0 = __ldcs(xa + 0 * 256 + q);
    float4 a1 = __ldcs(xa + 1 * 256 + q);
    float4 a2 = __ldcs(xa + 2 * 256 + q);
    float4 a3 = __ldcs(xa + 3 * 256 + q);
    float4 b0 = __ldcs(xb + 0 * 256 + q);
    float4 b1 = __ldcs(xb + 1 * 256 + q);
    float4 b2 = __ldcs(xb + 2 * 256 + q);
    float4 b3 = __ldcs(xb + 3 * 256 + q);

    // Wait for the sinkhorn kernel's trigger (overlapped with loads above).
    cudaGridDependencySynchronize();

    float h[16];
    #pragma unroll
    for (int i = 0; i < 16; i++) h[i] = __ldg(&g_H[i]);

    #pragma unroll
    for (int n = 0; n < 4; n++) {
        const float h0 = h[n * 4 + 0], h1 = h[n * 4 + 1];
        const float h2 = h[n * 4 + 2], h3 = h[n * 4 + 3];
        float4 o;
        o.x = h0 * a0.x + h1 * a1.x + h2 * a2.x + h3 * a3.x;
        o.y = h0 * a0.y + h1 * a1.y + h2 * a2.y + h3 * a3.y;
        o.z = h0 * a0.z + h1 * a1.z + h2 * a2.z + h3 * a3.z;
        o.w = h0 * a0.w + h1 * a1.w + h2 * a2.w + h3 * a3.w;
        __stcs(oa + n * 256 + q, o);
    }
    #pragma unroll
    for (int n = 0; n < 4; n++) {
        const float h0 = h[n * 4 + 0], h1 = h[n * 4 + 1];
        const float h2 = h[n * 4 + 2], h3 = h[n * 4 + 3];
        float4 o;
        o.x = h0 * b0.x + h1 * b1.x + h2 * b2.x + h3 * b3.x;
        o.y = h0 * b0.y + h1 * b1.y + h2 * b2.y + h3 * b3.y;
        o.z = h0 * b0.z + h1 * b1.z + h2 * b2.z + h3 * b3.z;
        o.w = h0 * b0.w + h1 * b1.w + h2 * b2.w + h3 * b3.w;
        __stcs(ob + n * 256 + q, o);
    }
}

extern "C" void kernel_launch(void* const* d_in, const int* in_sizes, int n_in,
                              void* d_out, int out_size) {
    const float* x     = (const float*)d_in[0];  // [4, 4096, 4, 1024] fp32
    const float* H_raw = (const float*)d_in[1];  // [4, 4]
    float* out         = (float*)d_out;          // same shape as x

    sinkhorn_kernel<<<1, 32>>>(H_raw);

    const int BT = 4 * 4096;  // 16384 (b,t) pairs, 2 per block

    // Launch mix with Programmatic Dependent Launch so it overlaps with the
    // sinkhorn kernel; mix blocks wait via cudaGridDependencySynchronize()
    // only after their loads are in flight.
    cudaLaunchConfig_t cfg = {};
    cfg.gridDim  = dim3(BT / 2, 1, 1);
    cfg.blockDim = dim3(256, 1, 1);
    cfg.dynamicSmemBytes = 0;
    cfg.stream = 0;
    cudaLaunchAttribute attr[1];
    attr[0].id = cudaLaunchAttributeProgrammaticStreamSerialization;
    attr[0].val.programmaticStreamSerializationAllowed = 1;
    cfg.attrs = attr;
    cfg.numAttrs = 1;

    cudaLaunchKernelEx(&cfg, mix_kernel, (const float4*)x, (float4*)out);
    (void)in_sizes; (void)n_in; (void)out_size;
}